// round 15
// baseline (speedup 1.0000x reference)
#include <cuda_runtime.h>
#include <cuda_bf16.h>
#include <math.h>
#include <stdint.h>

#define TSEQ  4096
#define HID   512
#define NCH   512
#define NHEAD 64
#define NPAIR 256
#define CHUNK 16
#define NCHUNK 256
#define NTILE 32

// ---------------- device scratch ----------------
__device__ __align__(16) __nv_bfloat16 g_W1h[NCH * HID];   // [r][k]
__device__ __align__(16) __nv_bfloat16 g_W1l[NCH * HID];
__device__ __align__(16) __nv_bfloat16 g_Ch[HID * NCH];    // [dd][r]
__device__ __align__(16) __nv_bfloat16 g_Cl[HID * NCH];
__device__ __align__(16) __nv_bfloat16 g_XTh[TSEQ * HID];  // [t][k]
__device__ __align__(16) __nv_bfloat16 g_XTl[TSEQ * HID];
__device__ __align__(16) float g_U[TSEQ * NCH];            // [t][r]
__device__ __align__(16) __nv_bfloat16 g_Yh[TSEQ * NCH];   // [t][r]
__device__ __align__(16) __nv_bfloat16 g_Yl[TSEQ * NCH];
__device__ __align__(16) float g_carryT[NCHUNK * NPAIR * 2];  // [chunk][pair]
__device__ __align__(16) float g_super[NTILE * NPAIR * 2];    // [tile][pair]
__device__ float g_pair[NPAIR * 8];   // g, cth, sth, th, g16, c16, s16, pad

// ---------------- helpers ----------------
__device__ __forceinline__ uint32_t smem_u32(const void* p) {
    uint32_t a;
    asm("{ .reg .u64 t; cvta.to.shared.u64 t, %1; cvt.u32.u64 %0, t; }"
        : "=r"(a) : "l"(p));
    return a;
}
__device__ __forceinline__ void cp16(uint32_t s, const void* g) {
    asm volatile("cp.async.cg.shared.global [%0], [%1], 16;" :: "r"(s), "l"(g));
}
__device__ __forceinline__ void cp_commit() { asm volatile("cp.async.commit_group;"); }
__device__ __forceinline__ void cp_wait2()  { asm volatile("cp.async.wait_group 2;"); }
__device__ __forceinline__ void cp_wait1()  { asm volatile("cp.async.wait_group 1;"); }
__device__ __forceinline__ void cp_wait0()  { asm volatile("cp.async.wait_group 0;"); }

__device__ __forceinline__ void ldm4(uint32_t* r, uint32_t a) {
    asm volatile("ldmatrix.sync.aligned.m8n8.x4.shared.b16 {%0,%1,%2,%3}, [%4];"
                 : "=r"(r[0]), "=r"(r[1]), "=r"(r[2]), "=r"(r[3]) : "r"(a));
}
__device__ __forceinline__ void mma16816(float* d, const uint32_t* a, const uint32_t* b) {
    asm volatile(
        "mma.sync.aligned.m16n8k16.row.col.f32.bf16.bf16.f32 "
        "{%0,%1,%2,%3}, {%4,%5,%6,%7}, {%8,%9}, {%0,%1,%2,%3};"
        : "+f"(d[0]), "+f"(d[1]), "+f"(d[2]), "+f"(d[3])
        : "r"(a[0]), "r"(a[1]), "r"(a[2]), "r"(a[3]), "r"(b[0]), "r"(b[1]));
}
__device__ __forceinline__ void bf16_split(float x, __nv_bfloat16& h, __nv_bfloat16& l) {
    h = __float2bfloat16_rn(x);
    l = __float2bfloat16_rn(x - __bfloat162float(h));
}
__device__ __forceinline__ float2 ldg64(const float2* p) {
    float2 v;
    asm volatile("ld.global.v2.f32 {%0,%1}, [%2];" : "=f"(v.x), "=f"(v.y) : "l"(p));
    return v;
}
__device__ __forceinline__ float2 cmul(float2 a, float2 b) {
    return make_float2(a.x*b.x - a.y*b.y, a.x*b.y + a.y*b.x);
}

// ============================================================
// init: blocks [0,64) = per-head setup; [64,2112) = transpose/split.
// ============================================================
__global__ __launch_bounds__(256) void init(const float* __restrict__ theta_log,
                                            const float* __restrict__ P,
                                            const float* __restrict__ gamma_log,
                                            const float* __restrict__ Bmat,
                                            const float* __restrict__ Cmat,
                                            const float* __restrict__ X) {
    int t = threadIdx.x;

    if (blockIdx.x >= 64) {
        __shared__ float t32[32][33];
        int b = blockIdx.x - 64;
        int tb = b & 127;
        int kb = b >> 7;
        int tx = t & 31, ty = t >> 5;
#pragma unroll
        for (int i = 0; i < 4; i++)
            t32[ty + 8*i][tx] = X[(size_t)(kb*32 + ty + 8*i) * TSEQ + tb*32 + tx];
        __syncthreads();
#pragma unroll
        for (int i = 0; i < 4; i++) {
            float v = t32[tx][ty + 8*i];
            __nv_bfloat16 hi, lo; bf16_split(v, hi, lo);
            size_t o = (size_t)(tb*32 + ty + 8*i) * HID + kb*32 + tx;
            g_XTh[o] = hi;
            g_XTl[o] = lo;
        }
        return;
    }

    int h = blockIdx.x;
    bool act = t < 64;
    int i = t >> 3, j = t & 7;
    __shared__ float sA[64], sT[64], sE[64];
    __shared__ float red[256];

    if (act) {
        sA[t] = 0.25f * (P[(h*8 + i)*8 + j] - P[(h*8 + j)*8 + i]);
        float id = (i == j) ? 1.f : 0.f;
        sT[t] = id;
        sE[t] = id;
    }
    __syncthreads();

    for (int k = 1; k <= 12; k++) {
        float s = 0.f;
        if (act) {
#pragma unroll
            for (int l = 0; l < 8; l++) s += sT[i*8 + l] * sA[l*8 + j];
            s *= (1.f / (float)k);
        }
        __syncthreads();
        if (act) { sT[t] = s; sE[t] += s; }
        __syncthreads();
    }
    float s1 = 0.f;
    if (act) {
#pragma unroll
        for (int l = 0; l < 8; l++) s1 += sE[i*8 + l] * sE[l*8 + j];
    }
    __syncthreads();
    if (act) sT[t] = s1;
    __syncthreads();
    float s2 = 0.f;
    if (act) {
#pragma unroll
        for (int l = 0; l < 8; l++) s2 += sT[i*8 + l] * sT[l*8 + j];
    }
    __syncthreads();
    if (act) sA[t] = s2;      // sA = final Pm

    const float4* bp = (const float4*)(Bmat + h * 8 * HID);
    float acc = 0.f;
#pragma unroll
    for (int e = 0; e < 4; e++) {
        float4 v = bp[t + e * 256];
        acc += v.x*v.x + v.y*v.y + v.z*v.z + v.w*v.w;
    }
    red[t] = acc;
    __syncthreads();
    for (int s = 128; s > 0; s >>= 1) {
        if (t < s) red[t] += red[t + s];
        __syncthreads();
    }

    float g = expf(-expf(gamma_log[h]));
    float nrm = sqrtf((1.f - g * g) / red[0]);

    if (t < 4) {
        float g2 = g*g, g4 = g2*g2, g8 = g4*g4, g16 = g8*g8;
        float th = expf(theta_log[h*4 + t]);
        float th16 = 16.f * th;
        int p = h*4 + t;
        g_pair[p*8 + 0] = g;
        g_pair[p*8 + 1] = cosf(th);
        g_pair[p*8 + 2] = sinf(th);
        g_pair[p*8 + 3] = th;
        g_pair[p*8 + 4] = g16;
        g_pair[p*8 + 5] = cosf(th16);
        g_pair[p*8 + 6] = sinf(th16);
        g_pair[p*8 + 7] = 0.f;
    }

#pragma unroll
    for (int e = 0; e < 4; e++) {
        int q = t + e * 256;
        int N = q >> 7;
        int d4 = (q & 127) << 2;
        const float* pm = &sA[N*8];
        float4 a = make_float4(0.f, 0.f, 0.f, 0.f);
#pragma unroll
        for (int n = 0; n < 8; n++) {
            float4 bv = *(const float4*)&Bmat[(size_t)(h*8 + n) * HID + d4];
            float w = pm[n];
            a.x = fmaf(w, bv.x, a.x); a.y = fmaf(w, bv.y, a.y);
            a.z = fmaf(w, bv.z, a.z); a.w = fmaf(w, bv.w, a.w);
        }
        float v[4] = {a.x*nrm, a.y*nrm, a.z*nrm, a.w*nrm};
        __nv_bfloat16 hh[4], ll[4];
#pragma unroll
        for (int k = 0; k < 4; k++) bf16_split(v[k], hh[k], ll[k]);
        int r = h*8 + N;
        *(__nv_bfloat162*)&g_W1h[r*HID + d4]     = __nv_bfloat162(hh[0], hh[1]);
        *(__nv_bfloat162*)&g_W1h[r*HID + d4 + 2] = __nv_bfloat162(hh[2], hh[3]);
        *(__nv_bfloat162*)&g_W1l[r*HID + d4]     = __nv_bfloat162(ll[0], ll[1]);
        *(__nv_bfloat162*)&g_W1l[r*HID + d4 + 2] = __nv_bfloat162(ll[2], ll[3]);
    }

#pragma unroll
    for (int e = 0; e < 16; e++) {
        int q = t + e * 256;
        int dd = q >> 3;
        int N = q & 7;
        const float* pm = &sA[N*8];
        float4 c0 = *(const float4*)&Cmat[(size_t)dd * NCH + h*8];
        float4 c1 = *(const float4*)&Cmat[(size_t)dd * NCH + h*8 + 4];
        float s = pm[0]*c0.x + pm[1]*c0.y + pm[2]*c0.z + pm[3]*c0.w
                + pm[4]*c1.x + pm[5]*c1.y + pm[6]*c1.z + pm[7]*c1.w;
        __nv_bfloat16 hh, ll;
        bf16_split(s, hh, ll);
        g_Ch[(size_t)dd * NCH + h*8 + N] = hh;
        g_Cl[(size_t)dd * NCH + h*8 + N] = ll;
    }
}

// ============================================================
// bf16 3-MMA split GEMM, 512 threads (16 warps, warp tile 64x16),
// 4-stage cp.async.
// MODE 0: U + chunk carries + tile super-carries; MODE 1: out + D*x.
// ============================================================
#define PITCHB 80
#define ARRB   (128*PITCHB)   // 10240
#define STAGEB (4*ARRB)       // 40960
#define NSTAGE 4
#define PITCHF 136
#define SC_OFF 73728

template <int MODE>
__global__ __launch_bounds__(512, 1)
void gemm_mma(const __nv_bfloat16* __restrict__ Ah, const __nv_bfloat16* __restrict__ Al,
              const __nv_bfloat16* __restrict__ Bh, const __nv_bfloat16* __restrict__ Bl,
              float* __restrict__ Cout,
              const __nv_bfloat16* __restrict__ Xh, const __nv_bfloat16* __restrict__ Xl,
              const float* __restrict__ Dv) {
    extern __shared__ char smem[];
    uint32_t sb = smem_u32(smem);
    int tid = threadIdx.x, lane = tid & 31, wid = tid >> 5;   // 16 warps
    int m0 = blockIdx.x * 128, n0 = blockIdx.y * 128;
    int m_w = (wid & 1) * 64;          // 2 m-halves
    int n_w = (wid >> 1) * 16;         // 8 n-slices of 16

    const __nv_bfloat16* gp[4] = {Ah, Al, Bh, Bl};

    auto load_stage = [&](int s, int k0) {
        uint32_t base = sb + s * STAGEB;
        int row = tid >> 2, q = tid & 3;
#pragma unroll
        for (int a = 0; a < 4; a++) {
            int row0 = (a < 2) ? m0 : n0;
            cp16(base + a * ARRB + row * PITCHB + q * 16,
                 gp[a] + (size_t)(row0 + row) * 512 + k0 + q * 8);
        }
    };

    float acc[4][2][4];
#pragma unroll
    for (int i = 0; i < 4; i++)
#pragma unroll
        for (int j = 0; j < 2; j++)
#pragma unroll
            for (int q = 0; q < 4; q++) acc[i][j][q] = 0.f;

    load_stage(0, 0);  cp_commit();
    load_stage(1, 32); cp_commit();
    load_stage(2, 64); cp_commit();

#pragma unroll 1
    for (int kt = 0; kt < 16; kt++) {
        if (kt <= 13) cp_wait2();
        else if (kt == 14) cp_wait1();
        else cp_wait0();
        __syncthreads();
        if (kt + 3 < 16) {
            load_stage((kt + 3) & 3, (kt + 3) * 32);
            cp_commit();
        }
        uint32_t base = sb + (kt & 3) * STAGEB;
#pragma unroll
        for (int kk = 0; kk < 2; kk++) {
            int cb = kk * 32;
            uint32_t ah[4][4], al[4][4], bh[4], bl[4];
#pragma unroll
            for (int i = 0; i < 4; i++) {
                int row = m_w + 16*i + (lane & 15);
                uint32_t ad = base + row * PITCHB + cb + 16 * (lane >> 4);
                ldm4(ah[i], ad);
                ldm4(al[i], ad + ARRB);
            }
            {
                int n = n_w + (lane & 7) + 8 * (lane >> 4);
                uint32_t ad = base + 2 * ARRB + n * PITCHB + cb + 16 * ((lane >> 3) & 1);
                ldm4(bh, ad);
                ldm4(bl, ad + ARRB);
            }
#pragma unroll
            for (int i = 0; i < 4; i++)
#pragma unroll
                for (int j = 0; j < 2; j++)
                    mma16816(acc[i][j], ah[i], &bh[j * 2]);
#pragma unroll
            for (int i = 0; i < 4; i++)
#pragma unroll
                for (int j = 0; j < 2; j++)
                    mma16816(acc[i][j], ah[i], &bl[j * 2]);
#pragma unroll
            for (int i = 0; i < 4; i++)
#pragma unroll
                for (int j = 0; j < 2; j++)
                    mma16816(acc[i][j], al[i], &bh[j * 2]);
        }
    }

    int rh = lane >> 2, c2 = (lane & 3) * 2;

    if (MODE == 1) {
        float dvx[2], dvy[2];
#pragma unroll
        for (int j = 0; j < 2; j++) {
            int col = n0 + n_w + 8*j + c2;
            dvx[j] = Dv[col];
            dvy[j] = Dv[col + 1];
        }
#pragma unroll
        for (int i = 0; i < 4; i++) {
            int row = m0 + m_w + 16*i + rh;
#pragma unroll
            for (int j = 0; j < 2; j++) {
                int col = n0 + n_w + 8*j + c2;
                size_t o0 = (size_t)row * 512 + col;
                size_t o1 = (size_t)(row + 8) * 512 + col;
                __nv_bfloat162 xh0 = *(const __nv_bfloat162*)&Xh[o0];
                __nv_bfloat162 xl0 = *(const __nv_bfloat162*)&Xl[o0];
                __nv_bfloat162 xh1 = *(const __nv_bfloat162*)&Xh[o1];
                __nv_bfloat162 xl1 = *(const __nv_bfloat162*)&Xl[o1];
                float x00 = __bfloat162float(xh0.x) + __bfloat162float(xl0.x);
                float x01 = __bfloat162float(xh0.y) + __bfloat162float(xl0.y);
                float x10 = __bfloat162float(xh1.x) + __bfloat162float(xl1.x);
                float x11 = __bfloat162float(xh1.y) + __bfloat162float(xl1.y);
                *(float2*)&Cout[o0] = make_float2(fmaf(dvx[j], x00, acc[i][j][0]),
                                                  fmaf(dvy[j], x01, acc[i][j][1]));
                *(float2*)&Cout[o1] = make_float2(fmaf(dvx[j], x10, acc[i][j][2]),
                                                  fmaf(dvy[j], x11, acc[i][j][3]));
            }
        }
        return;
    }

    // ---------------- MODE 0 epilogue ----------------
    __syncthreads();
    float* Us = (float*)smem;   // [128][PITCHF]
#pragma unroll
    for (int i = 0; i < 4; i++) {
        int row = m_w + 16*i + rh;
#pragma unroll
        for (int j = 0; j < 2; j++) {
            int col = n_w + 8*j + c2;
            *(float2*)&Us[row * PITCHF + col]       = make_float2(acc[i][j][0], acc[i][j][1]);
            *(float2*)&Us[(row + 8) * PITCHF + col] = make_float2(acc[i][j][2], acc[i][j][3]);
        }
    }
    __syncthreads();

#pragma unroll
    for (int e = 0; e < 8; e++) {
        int idx = tid + e * 512;
        int t = idx >> 5, c4 = (idx & 31) << 2;
        float4 v = *(float4*)&Us[t * PITCHF + c4];
        *(float4*)&Cout[(size_t)(m0 + t) * 512 + n0 + c4] = v;
    }

    // per-chunk carries: 8 chunks x 64 pairs = 512 units, one per thread
    float2* sc = (float2*)(smem + SC_OFF);
    {
        int pl = tid & 63, ch = tid >> 6;
        int P = (n0 >> 1) + pl;
        float g  = g_pair[P*8 + 0];
        float gc = g * g_pair[P*8 + 1];
        float gs = g * g_pair[P*8 + 2];
        float a = 0.f, bb = 0.f;
        const float* src = &Us[(ch * 16) * PITCHF + 2 * pl];
#pragma unroll
        for (int i = 0; i < 16; i++) {
            float2 uu = *(const float2*)(src + i * PITCHF);
            float na = fmaf(gc, a, fmaf(-gs, bb, uu.x));
            float nb = fmaf(gs, a, fmaf( gc, bb, uu.y));
            a = na; bb = nb;
        }
        int C = (blockIdx.x << 3) + ch;
        *(float2*)&g_carryT[(C * NPAIR + P) * 2] = make_float2(a, bb);
        sc[ch * 64 + pl] = make_float2(a, bb);
    }
    __syncthreads();

    if (tid < 64) {
        int pl = tid;
        int P = (n0 >> 1) + pl;
        float Mx = g_pair[P*8 + 4] * g_pair[P*8 + 5];
        float My = g_pair[P*8 + 4] * g_pair[P*8 + 6];
        float2 v = sc[pl];
#pragma unroll
        for (int e = 1; e < 8; e++) {
            float2 cb2 = sc[e * 64 + pl];
            v = make_float2(fmaf(Mx, v.x, fmaf(-My, v.y, cb2.x)),
                            fmaf(Mx, v.y, fmaf( My, v.x, cb2.y)));
        }
        *(float2*)&g_super[((int)blockIdx.x * NPAIR + P) * 2] = v;
    }
}

// ============================================================
// scan3: block c handles rows [c*16, c*16+16); thread p = pair.
// ============================================================
__global__ __launch_bounds__(256, 1) void scan3() {
    int c = blockIdx.x;
    int p = threadIdx.x;
    int tb = c >> 3;
    int ci = c & 7;

    float g  = g_pair[p*8 + 0];
    float gc = g * g_pair[p*8 + 1];
    float gs = g * g_pair[p*8 + 2];
    float2 M = make_float2(g_pair[p*8 + 4] * g_pair[p*8 + 5],
                           g_pair[p*8 + 4] * g_pair[p*8 + 6]);
    float2 M8 = cmul(M, M); M8 = cmul(M8, M8); M8 = cmul(M8, M8);

    float a = 0.f, b = 0.f;
    float2 ub[8];

    {
        const float2* sp = (const float2*)g_super + p;
        int k = 0;
#pragma unroll 1
        for (; k + 8 <= tb; k += 8) {
#pragma unroll
            for (int e = 0; e < 8; e++) ub[e] = ldg64(sp + (k + e) * NPAIR);
#pragma unroll
            for (int e = 0; e < 8; e++) {
                float na = fmaf(M8.x, a, fmaf(-M8.y, b, ub[e].x));
                float nb = fmaf(M8.x, b, fmaf( M8.y, a, ub[e].y));
                a = na; b = nb;
            }
        }
#pragma unroll 1
        for (; k < tb; k++) {
            float2 v = ldg64(sp + k * NPAIR);
            float na = fmaf(M8.x, a, fmaf(-M8.y, b, v.x));
            float nb = fmaf(M8.x, b, fmaf( M8.y, a, v.y));
            a = na; b = nb;
        }
    }
    {
        const float2* cp = (const float2*)g_carryT + (size_t)(tb * 8) * NPAIR + p;
#pragma unroll 1
        for (int k = 0; k < ci; k++) {
            float2 v = ldg64(cp + k * NPAIR);
            float na = fmaf(M.x, a, fmaf(-M.y, b, v.x));
            float nb = fmaf(M.x, b, fmaf( M.y, a, v.y));
            a = na; b = nb;
        }
    }

    const float2* up = (const float2*)(g_U + (size_t)(c * CHUNK) * NCH) + p;
    __nv_bfloat162* yh = (__nv_bfloat162*)(g_Yh + (size_t)(c * CHUNK) * NCH) + p;
    __nv_bfloat162* yl = (__nv_bfloat162*)(g_Yl + (size_t)(c * CHUNK) * NCH) + p;

#pragma unroll
    for (int base = 0; base < CHUNK; base += 8) {
#pragma unroll
        for (int e = 0; e < 8; e++) ub[e] = ldg64(up + (base + e) * 256);
#pragma unroll
        for (int e = 0; e < 8; e++) {
            float na = fmaf(gc, a, fmaf(-gs, b, ub[e].x));
            float nb = fmaf(gs, a, fmaf( gc, b, ub[e].y));
            a = na; b = nb;
            __nv_bfloat16 ha, la, hb, lb;
            bf16_split(a, ha, la);
            bf16_split(b, hb, lb);
            yh[(base + e) * 256] = __nv_bfloat162(ha, hb);
            yl[(base + e) * 256] = __nv_bfloat162(la, lb);
        }
    }
}

// ============================================================
extern "C" void kernel_launch(void* const* d_in, const int* in_sizes, int n_in,
                              void* d_out, int out_size) {
    const float* X         = (const float*)d_in[0];
    const float* theta_log = (const float*)d_in[1];
    const float* P         = (const float*)d_in[2];
    const float* Bmat      = (const float*)d_in[3];
    const float* Cmat      = (const float*)d_in[4];
    const float* Dv        = (const float*)d_in[5];
    const float* gamma_log = (const float*)d_in[6];
    float* out = (float*)d_out;

    const int GEMM_SMEM = NSTAGE * STAGEB;   // 163840
    cudaFuncSetAttribute(gemm_mma<0>, cudaFuncAttributeMaxDynamicSharedMemorySize, GEMM_SMEM);
    cudaFuncSetAttribute(gemm_mma<1>, cudaFuncAttributeMaxDynamicSharedMemorySize, GEMM_SMEM);

    init<<<2112, 256>>>(theta_log, P, gamma_log, Bmat, Cmat, X);

    float* U;   cudaGetSymbolAddress((void**)&U, g_U);
    __nv_bfloat16 *XTh, *XTl, *W1h, *W1l, *Yh, *Yl, *Ch, *Cl;
    cudaGetSymbolAddress((void**)&XTh, g_XTh);
    cudaGetSymbolAddress((void**)&XTl, g_XTl);
    cudaGetSymbolAddress((void**)&W1h, g_W1h);
    cudaGetSymbolAddress((void**)&W1l, g_W1l);
    cudaGetSymbolAddress((void**)&Yh, g_Yh);
    cudaGetSymbolAddress((void**)&Yl, g_Yl);
    cudaGetSymbolAddress((void**)&Ch, g_Ch);
    cudaGetSymbolAddress((void**)&Cl, g_Cl);

    dim3 gg(TSEQ / 128, NCH / 128);   // (32, 4)
    gemm_mma<0><<<gg, 512, GEMM_SMEM>>>(XTh, XTl, W1h, W1l, U, nullptr, nullptr, nullptr);
    scan3<<<NCHUNK, 256>>>();
    gemm_mma<1><<<gg, 512, GEMM_SMEM>>>(Yh, Yl, Ch, Cl, out, XTh, XTl, Dv);
}

// round 16
// speedup vs baseline: 1.0842x; 1.0842x over previous
#include <cuda_runtime.h>
#include <cuda_bf16.h>
#include <math.h>
#include <stdint.h>

#define TSEQ  4096
#define HID   512
#define NCH   512
#define NHEAD 64
#define NPAIR 256
#define CHUNK 16
#define NCHUNK 256
#define NTILE 32

// ---------------- device scratch ----------------
__device__ __align__(16) __nv_bfloat16 g_W1h[NCH * HID];   // [r][k]
__device__ __align__(16) __nv_bfloat16 g_W1l[NCH * HID];
__device__ __align__(16) __nv_bfloat16 g_Ch[HID * NCH];    // [dd][r]
__device__ __align__(16) __nv_bfloat16 g_Cl[HID * NCH];
__device__ __align__(16) __nv_bfloat16 g_XTh[TSEQ * HID];  // [t][k]
__device__ __align__(16) __nv_bfloat16 g_XTl[TSEQ * HID];
__device__ __align__(16) float g_U[TSEQ * NCH];            // [t][r]
__device__ __align__(16) __nv_bfloat16 g_Yh[TSEQ * NCH];   // [t][r]
__device__ __align__(16) __nv_bfloat16 g_Yl[TSEQ * NCH];
__device__ __align__(16) float g_carryT[NCHUNK * NPAIR * 2];  // [chunk][pair]
__device__ __align__(16) float g_super[NTILE * NPAIR * 2];    // [tile][pair]
__device__ float g_pair[NPAIR * 8];   // g, cth, sth, th, g16, c16, s16, pad

// ---------------- helpers ----------------
__device__ __forceinline__ uint32_t smem_u32(const void* p) {
    uint32_t a;
    asm("{ .reg .u64 t; cvta.to.shared.u64 t, %1; cvt.u32.u64 %0, t; }"
        : "=r"(a) : "l"(p));
    return a;
}
__device__ __forceinline__ void cp16(uint32_t s, const void* g) {
    asm volatile("cp.async.cg.shared.global [%0], [%1], 16;" :: "r"(s), "l"(g));
}
__device__ __forceinline__ void cp_commit() { asm volatile("cp.async.commit_group;"); }
__device__ __forceinline__ void cp_wait2()  { asm volatile("cp.async.wait_group 2;"); }
__device__ __forceinline__ void cp_wait1()  { asm volatile("cp.async.wait_group 1;"); }
__device__ __forceinline__ void cp_wait0()  { asm volatile("cp.async.wait_group 0;"); }

__device__ __forceinline__ void ldm4(uint32_t* r, uint32_t a) {
    asm volatile("ldmatrix.sync.aligned.m8n8.x4.shared.b16 {%0,%1,%2,%3}, [%4];"
                 : "=r"(r[0]), "=r"(r[1]), "=r"(r[2]), "=r"(r[3]) : "r"(a));
}
__device__ __forceinline__ void mma16816(float* d, const uint32_t* a, const uint32_t* b) {
    asm volatile(
        "mma.sync.aligned.m16n8k16.row.col.f32.bf16.bf16.f32 "
        "{%0,%1,%2,%3}, {%4,%5,%6,%7}, {%8,%9}, {%0,%1,%2,%3};"
        : "+f"(d[0]), "+f"(d[1]), "+f"(d[2]), "+f"(d[3])
        : "r"(a[0]), "r"(a[1]), "r"(a[2]), "r"(a[3]), "r"(b[0]), "r"(b[1]));
}
__device__ __forceinline__ void bf16_split(float x, __nv_bfloat16& h, __nv_bfloat16& l) {
    h = __float2bfloat16_rn(x);
    l = __float2bfloat16_rn(x - __bfloat162float(h));
}
__device__ __forceinline__ float2 ldg64(const float2* p) {
    float2 v;
    asm volatile("ld.global.v2.f32 {%0,%1}, [%2];" : "=f"(v.x), "=f"(v.y) : "l"(p));
    return v;
}
__device__ __forceinline__ float2 cmul(float2 a, float2 b) {
    return make_float2(a.x*b.x - a.y*b.y, a.x*b.y + a.y*b.x);
}

// ============================================================
// init: blocks [0,64) = per-head setup; [64,2112) = transpose/split.
// ============================================================
__global__ __launch_bounds__(256) void init(const float* __restrict__ theta_log,
                                            const float* __restrict__ P,
                                            const float* __restrict__ gamma_log,
                                            const float* __restrict__ Bmat,
                                            const float* __restrict__ Cmat,
                                            const float* __restrict__ X) {
    int t = threadIdx.x;

    if (blockIdx.x >= 64) {
        __shared__ float t32[32][33];
        int b = blockIdx.x - 64;
        int tb = b & 127;
        int kb = b >> 7;
        int tx = t & 31, ty = t >> 5;
#pragma unroll
        for (int i = 0; i < 4; i++)
            t32[ty + 8*i][tx] = X[(size_t)(kb*32 + ty + 8*i) * TSEQ + tb*32 + tx];
        __syncthreads();
#pragma unroll
        for (int i = 0; i < 4; i++) {
            float v = t32[tx][ty + 8*i];
            __nv_bfloat16 hi, lo; bf16_split(v, hi, lo);
            size_t o = (size_t)(tb*32 + ty + 8*i) * HID + kb*32 + tx;
            g_XTh[o] = hi;
            g_XTl[o] = lo;
        }
        return;
    }

    int h = blockIdx.x;
    bool act = t < 64;
    int i = t >> 3, j = t & 7;
    __shared__ float sA[64], sT[64], sE[64];
    __shared__ float red[256];

    if (act) {
        sA[t] = 0.25f * (P[(h*8 + i)*8 + j] - P[(h*8 + j)*8 + i]);
        float id = (i == j) ? 1.f : 0.f;
        sT[t] = id;
        sE[t] = id;
    }
    __syncthreads();

    for (int k = 1; k <= 12; k++) {
        float s = 0.f;
        if (act) {
#pragma unroll
            for (int l = 0; l < 8; l++) s += sT[i*8 + l] * sA[l*8 + j];
            s *= (1.f / (float)k);
        }
        __syncthreads();
        if (act) { sT[t] = s; sE[t] += s; }
        __syncthreads();
    }
    float s1 = 0.f;
    if (act) {
#pragma unroll
        for (int l = 0; l < 8; l++) s1 += sE[i*8 + l] * sE[l*8 + j];
    }
    __syncthreads();
    if (act) sT[t] = s1;
    __syncthreads();
    float s2 = 0.f;
    if (act) {
#pragma unroll
        for (int l = 0; l < 8; l++) s2 += sT[i*8 + l] * sT[l*8 + j];
    }
    __syncthreads();
    if (act) sA[t] = s2;      // sA = final Pm

    const float4* bp = (const float4*)(Bmat + h * 8 * HID);
    float acc = 0.f;
#pragma unroll
    for (int e = 0; e < 4; e++) {
        float4 v = bp[t + e * 256];
        acc += v.x*v.x + v.y*v.y + v.z*v.z + v.w*v.w;
    }
    red[t] = acc;
    __syncthreads();
    for (int s = 128; s > 0; s >>= 1) {
        if (t < s) red[t] += red[t + s];
        __syncthreads();
    }

    float g = expf(-expf(gamma_log[h]));
    float nrm = sqrtf((1.f - g * g) / red[0]);

    if (t < 4) {
        float g2 = g*g, g4 = g2*g2, g8 = g4*g4, g16 = g8*g8;
        float th = expf(theta_log[h*4 + t]);
        float th16 = 16.f * th;
        int p = h*4 + t;
        g_pair[p*8 + 0] = g;
        g_pair[p*8 + 1] = cosf(th);
        g_pair[p*8 + 2] = sinf(th);
        g_pair[p*8 + 3] = th;
        g_pair[p*8 + 4] = g16;
        g_pair[p*8 + 5] = cosf(th16);
        g_pair[p*8 + 6] = sinf(th16);
        g_pair[p*8 + 7] = 0.f;
    }

#pragma unroll
    for (int e = 0; e < 4; e++) {
        int q = t + e * 256;
        int N = q >> 7;
        int d4 = (q & 127) << 2;
        const float* pm = &sA[N*8];
        float4 a = make_float4(0.f, 0.f, 0.f, 0.f);
#pragma unroll
        for (int n = 0; n < 8; n++) {
            float4 bv = *(const float4*)&Bmat[(size_t)(h*8 + n) * HID + d4];
            float w = pm[n];
            a.x = fmaf(w, bv.x, a.x); a.y = fmaf(w, bv.y, a.y);
            a.z = fmaf(w, bv.z, a.z); a.w = fmaf(w, bv.w, a.w);
        }
        float v[4] = {a.x*nrm, a.y*nrm, a.z*nrm, a.w*nrm};
        __nv_bfloat16 hh[4], ll[4];
#pragma unroll
        for (int k = 0; k < 4; k++) bf16_split(v[k], hh[k], ll[k]);
        int r = h*8 + N;
        *(__nv_bfloat162*)&g_W1h[r*HID + d4]     = __nv_bfloat162(hh[0], hh[1]);
        *(__nv_bfloat162*)&g_W1h[r*HID + d4 + 2] = __nv_bfloat162(hh[2], hh[3]);
        *(__nv_bfloat162*)&g_W1l[r*HID + d4]     = __nv_bfloat162(ll[0], ll[1]);
        *(__nv_bfloat162*)&g_W1l[r*HID + d4 + 2] = __nv_bfloat162(ll[2], ll[3]);
    }

#pragma unroll
    for (int e = 0; e < 16; e++) {
        int q = t + e * 256;
        int dd = q >> 3;
        int N = q & 7;
        const float* pm = &sA[N*8];
        float4 c0 = *(const float4*)&Cmat[(size_t)dd * NCH + h*8];
        float4 c1 = *(const float4*)&Cmat[(size_t)dd * NCH + h*8 + 4];
        float s = pm[0]*c0.x + pm[1]*c0.y + pm[2]*c0.z + pm[3]*c0.w
                + pm[4]*c1.x + pm[5]*c1.y + pm[6]*c1.z + pm[7]*c1.w;
        __nv_bfloat16 hh, ll;
        bf16_split(s, hh, ll);
        g_Ch[(size_t)dd * NCH + h*8 + N] = hh;
        g_Cl[(size_t)dd * NCH + h*8 + N] = ll;
    }
}

// ============================================================
// bf16 3-MMA split GEMM, 256 threads (warp tile 64x32), 4-stage
// cp.async, ALL 48 fragment loads hoisted per kt (single exposed
// ldsm latency, crossbar overlaps MMA issue).
// ============================================================
#define PITCHB 80
#define ARRB   (128*PITCHB)   // 10240
#define STAGEB (4*ARRB)       // 40960
#define NSTAGE 4
#define PITCHF 136
#define SC_OFF 73728

template <int MODE>
__global__ __launch_bounds__(256, 1)
void gemm_mma(const __nv_bfloat16* __restrict__ Ah, const __nv_bfloat16* __restrict__ Al,
              const __nv_bfloat16* __restrict__ Bh, const __nv_bfloat16* __restrict__ Bl,
              float* __restrict__ Cout,
              const __nv_bfloat16* __restrict__ Xh, const __nv_bfloat16* __restrict__ Xl,
              const float* __restrict__ Dv) {
    extern __shared__ char smem[];
    uint32_t sb = smem_u32(smem);
    int tid = threadIdx.x, lane = tid & 31, wid = tid >> 5;
    int m0 = blockIdx.x * 128, n0 = blockIdx.y * 128;
    int m_w = (wid & 1) * 64, n_w = (wid >> 1) * 32;

    const __nv_bfloat16* gp[4] = {Ah, Al, Bh, Bl};

    auto load_stage = [&](int s, int k0) {
        uint32_t base = sb + s * STAGEB;
#pragma unroll
        for (int a = 0; a < 4; a++) {
            int row0 = (a < 2) ? m0 : n0;
#pragma unroll
            for (int e = 0; e < 2; e++) {
                int idx = tid + e * 256;
                int row = idx >> 2, q = idx & 3;
                cp16(base + a * ARRB + row * PITCHB + q * 16,
                     gp[a] + (size_t)(row0 + row) * 512 + k0 + q * 8);
            }
        }
    };

    float acc[4][4][4];
#pragma unroll
    for (int i = 0; i < 4; i++)
#pragma unroll
        for (int j = 0; j < 4; j++)
#pragma unroll
            for (int q = 0; q < 4; q++) acc[i][j][q] = 0.f;

    load_stage(0, 0);  cp_commit();
    load_stage(1, 32); cp_commit();
    load_stage(2, 64); cp_commit();

#pragma unroll 1
    for (int kt = 0; kt < 16; kt++) {
        if (kt <= 13) cp_wait2();
        else if (kt == 14) cp_wait1();
        else cp_wait0();
        __syncthreads();
        if (kt + 3 < 16) {
            load_stage((kt + 3) & 3, (kt + 3) * 32);
            cp_commit();
        }
        uint32_t base = sb + (kt & 3) * STAGEB;

        // ---- hoist ALL fragment loads for both kk halves (48 ldm4) ----
        uint32_t ah[2][4][4], al[2][4][4], bh[2][2][4], bl[2][2][4];
#pragma unroll
        for (int kk = 0; kk < 2; kk++) {
            int cb = kk * 32;
#pragma unroll
            for (int i = 0; i < 4; i++) {
                int row = m_w + 16*i + (lane & 15);
                uint32_t ad = base + row * PITCHB + cb + 16 * (lane >> 4);
                ldm4(ah[kk][i], ad);
                ldm4(al[kk][i], ad + ARRB);
            }
#pragma unroll
            for (int j2 = 0; j2 < 2; j2++) {
                int n = n_w + 16*j2 + (lane & 7) + 8 * (lane >> 4);
                uint32_t ad = base + 2 * ARRB + n * PITCHB + cb + 16 * ((lane >> 3) & 1);
                ldm4(bh[kk][j2], ad);
                ldm4(bl[kk][j2], ad + ARRB);
            }
        }

        // ---- 96 MMAs, split-major within each kk (order preserved per acc) ----
#pragma unroll
        for (int kk = 0; kk < 2; kk++) {
#pragma unroll
            for (int i = 0; i < 4; i++)
#pragma unroll
                for (int j = 0; j < 4; j++)
                    mma16816(acc[i][j], ah[kk][i], &bh[kk][j >> 1][(j & 1) * 2]);
#pragma unroll
            for (int i = 0; i < 4; i++)
#pragma unroll
                for (int j = 0; j < 4; j++)
                    mma16816(acc[i][j], ah[kk][i], &bl[kk][j >> 1][(j & 1) * 2]);
#pragma unroll
            for (int i = 0; i < 4; i++)
#pragma unroll
                for (int j = 0; j < 4; j++)
                    mma16816(acc[i][j], al[kk][i], &bh[kk][j >> 1][(j & 1) * 2]);
        }
    }

    int rh = lane >> 2, c2 = (lane & 3) * 2;

    if (MODE == 1) {
        float dvx[4], dvy[4];
#pragma unroll
        for (int j = 0; j < 4; j++) {
            int col = n0 + n_w + 8*j + c2;
            dvx[j] = Dv[col];
            dvy[j] = Dv[col + 1];
        }
#pragma unroll
        for (int i = 0; i < 4; i++) {
            int row = m0 + m_w + 16*i + rh;
#pragma unroll
            for (int j = 0; j < 4; j++) {
                int col = n0 + n_w + 8*j + c2;
                size_t o0 = (size_t)row * 512 + col;
                size_t o1 = (size_t)(row + 8) * 512 + col;
                __nv_bfloat162 xh0 = *(const __nv_bfloat162*)&Xh[o0];
                __nv_bfloat162 xl0 = *(const __nv_bfloat162*)&Xl[o0];
                __nv_bfloat162 xh1 = *(const __nv_bfloat162*)&Xh[o1];
                __nv_bfloat162 xl1 = *(const __nv_bfloat162*)&Xl[o1];
                float x00 = __bfloat162float(xh0.x) + __bfloat162float(xl0.x);
                float x01 = __bfloat162float(xh0.y) + __bfloat162float(xl0.y);
                float x10 = __bfloat162float(xh1.x) + __bfloat162float(xl1.x);
                float x11 = __bfloat162float(xh1.y) + __bfloat162float(xl1.y);
                *(float2*)&Cout[o0] = make_float2(fmaf(dvx[j], x00, acc[i][j][0]),
                                                  fmaf(dvy[j], x01, acc[i][j][1]));
                *(float2*)&Cout[o1] = make_float2(fmaf(dvx[j], x10, acc[i][j][2]),
                                                  fmaf(dvy[j], x11, acc[i][j][3]));
            }
        }
        return;
    }

    // ---------------- MODE 0 epilogue ----------------
    __syncthreads();
    float* Us = (float*)smem;   // [128][PITCHF]
#pragma unroll
    for (int i = 0; i < 4; i++) {
        int row = m_w + 16*i + rh;
#pragma unroll
        for (int j = 0; j < 4; j++) {
            int col = n_w + 8*j + c2;
            *(float2*)&Us[row * PITCHF + col]       = make_float2(acc[i][j][0], acc[i][j][1]);
            *(float2*)&Us[(row + 8) * PITCHF + col] = make_float2(acc[i][j][2], acc[i][j][3]);
        }
    }
    __syncthreads();

#pragma unroll
    for (int e = 0; e < 16; e++) {
        int idx = tid + e * 256;
        int t = idx >> 5, c4 = (idx & 31) << 2;
        float4 v = *(float4*)&Us[t * PITCHF + c4];
        *(float4*)&Cout[(size_t)(m0 + t) * 512 + n0 + c4] = v;
    }

    float2* sc = (float2*)(smem + SC_OFF);
#pragma unroll
    for (int u0 = 0; u0 < 2; u0++) {
        int u = tid + u0 * 256;
        int pl = u & 63, ch = u >> 6;
        int P = (n0 >> 1) + pl;
        float g  = g_pair[P*8 + 0];
        float gc = g * g_pair[P*8 + 1];
        float gs = g * g_pair[P*8 + 2];
        float a = 0.f, bb = 0.f;
        const float* src = &Us[(ch * 16) * PITCHF + 2 * pl];
#pragma unroll
        for (int i = 0; i < 16; i++) {
            float2 uu = *(const float2*)(src + i * PITCHF);
            float na = fmaf(gc, a, fmaf(-gs, bb, uu.x));
            float nb = fmaf(gs, a, fmaf( gc, bb, uu.y));
            a = na; bb = nb;
        }
        int C = (blockIdx.x << 3) + ch;
        *(float2*)&g_carryT[(C * NPAIR + P) * 2] = make_float2(a, bb);
        sc[ch * 64 + pl] = make_float2(a, bb);
    }
    __syncthreads();

    if (tid < 64) {
        int pl = tid;
        int P = (n0 >> 1) + pl;
        float Mx = g_pair[P*8 + 4] * g_pair[P*8 + 5];
        float My = g_pair[P*8 + 4] * g_pair[P*8 + 6];
        float2 v = sc[pl];
#pragma unroll
        for (int e = 1; e < 8; e++) {
            float2 cb2 = sc[e * 64 + pl];
            v = make_float2(fmaf(Mx, v.x, fmaf(-My, v.y, cb2.x)),
                            fmaf(Mx, v.y, fmaf( My, v.x, cb2.y)));
        }
        *(float2*)&g_super[((int)blockIdx.x * NPAIR + P) * 2] = v;
    }
}

// ============================================================
// scan3: block c handles rows [c*16, c*16+16); thread p = pair.
// ============================================================
__global__ __launch_bounds__(256, 1) void scan3() {
    int c = blockIdx.x;
    int p = threadIdx.x;
    int tb = c >> 3;
    int ci = c & 7;

    float g  = g_pair[p*8 + 0];
    float gc = g * g_pair[p*8 + 1];
    float gs = g * g_pair[p*8 + 2];
    float2 M = make_float2(g_pair[p*8 + 4] * g_pair[p*8 + 5],
                           g_pair[p*8 + 4] * g_pair[p*8 + 6]);
    float2 M8 = cmul(M, M); M8 = cmul(M8, M8); M8 = cmul(M8, M8);

    float a = 0.f, b = 0.f;
    float2 ub[8];

    {
        const float2* sp = (const float2*)g_super + p;
        int k = 0;
#pragma unroll 1
        for (; k + 8 <= tb; k += 8) {
#pragma unroll
            for (int e = 0; e < 8; e++) ub[e] = ldg64(sp + (k + e) * NPAIR);
#pragma unroll
            for (int e = 0; e < 8; e++) {
                float na = fmaf(M8.x, a, fmaf(-M8.y, b, ub[e].x));
                float nb = fmaf(M8.x, b, fmaf( M8.y, a, ub[e].y));
                a = na; b = nb;
            }
        }
#pragma unroll 1
        for (; k < tb; k++) {
            float2 v = ldg64(sp + k * NPAIR);
            float na = fmaf(M8.x, a, fmaf(-M8.y, b, v.x));
            float nb = fmaf(M8.x, b, fmaf( M8.y, a, v.y));
            a = na; b = nb;
        }
    }
    {
        const float2* cp = (const float2*)g_carryT + (size_t)(tb * 8) * NPAIR + p;
#pragma unroll 1
        for (int k = 0; k < ci; k++) {
            float2 v = ldg64(cp + k * NPAIR);
            float na = fmaf(M.x, a, fmaf(-M.y, b, v.x));
            float nb = fmaf(M.x, b, fmaf( M.y, a, v.y));
            a = na; b = nb;
        }
    }

    const float2* up = (const float2*)(g_U + (size_t)(c * CHUNK) * NCH) + p;
    __nv_bfloat162* yh = (__nv_bfloat162*)(g_Yh + (size_t)(c * CHUNK) * NCH) + p;
    __nv_bfloat162* yl = (__nv_bfloat162*)(g_Yl + (size_t)(c * CHUNK) * NCH) + p;

#pragma unroll
    for (int base = 0; base < CHUNK; base += 8) {
#pragma unroll
        for (int e = 0; e < 8; e++) ub[e] = ldg64(up + (base + e) * 256);
#pragma unroll
        for (int e = 0; e < 8; e++) {
            float na = fmaf(gc, a, fmaf(-gs, b, ub[e].x));
            float nb = fmaf(gs, a, fmaf( gc, b, ub[e].y));
            a = na; b = nb;
            __nv_bfloat16 ha, la, hb, lb;
            bf16_split(a, ha, la);
            bf16_split(b, hb, lb);
            yh[(base + e) * 256] = __nv_bfloat162(ha, hb);
            yl[(base + e) * 256] = __nv_bfloat162(la, lb);
        }
    }
}

// ============================================================
extern "C" void kernel_launch(void* const* d_in, const int* in_sizes, int n_in,
                              void* d_out, int out_size) {
    const float* X         = (const float*)d_in[0];
    const float* theta_log = (const float*)d_in[1];
    const float* P         = (const float*)d_in[2];
    const float* Bmat      = (const float*)d_in[3];
    const float* Cmat      = (const float*)d_in[4];
    const float* Dv        = (const float*)d_in[5];
    const float* gamma_log = (const float*)d_in[6];
    float* out = (float*)d_out;

    const int GEMM_SMEM = NSTAGE * STAGEB;   // 163840
    cudaFuncSetAttribute(gemm_mma<0>, cudaFuncAttributeMaxDynamicSharedMemorySize, GEMM_SMEM);
    cudaFuncSetAttribute(gemm_mma<1>, cudaFuncAttributeMaxDynamicSharedMemorySize, GEMM_SMEM);

    init<<<2112, 256>>>(theta_log, P, gamma_log, Bmat, Cmat, X);

    float* U;   cudaGetSymbolAddress((void**)&U, g_U);
    __nv_bfloat16 *XTh, *XTl, *W1h, *W1l, *Yh, *Yl, *Ch, *Cl;
    cudaGetSymbolAddress((void**)&XTh, g_XTh);
    cudaGetSymbolAddress((void**)&XTl, g_XTl);
    cudaGetSymbolAddress((void**)&W1h, g_W1h);
    cudaGetSymbolAddress((void**)&W1l, g_W1l);
    cudaGetSymbolAddress((void**)&Yh, g_Yh);
    cudaGetSymbolAddress((void**)&Yl, g_Yl);
    cudaGetSymbolAddress((void**)&Ch, g_Ch);
    cudaGetSymbolAddress((void**)&Cl, g_Cl);

    dim3 gg(TSEQ / 128, NCH / 128);   // (32, 4)
    gemm_mma<0><<<gg, 256, GEMM_SMEM>>>(XTh, XTl, W1h, W1l, U, nullptr, nullptr, nullptr);
    scan3<<<NCHUNK, 256>>>();
    gemm_mma<1><<<gg, 256, GEMM_SMEM>>>(Yh, Yl, Ch, Cl, out, XTh, XTl, Dv);
}

// round 17
// speedup vs baseline: 1.2868x; 1.1869x over previous
#include <cuda_runtime.h>
#include <cuda_fp16.h>
#include <math.h>
#include <stdint.h>

#define TSEQ  4096
#define HID   512
#define NCH   512
#define NHEAD 64
#define NPAIR 256
#define CHUNK 16
#define NCHUNK 256
#define NTILE 32

// ---------------- device scratch ----------------
__device__ __align__(16) __half g_W1[NCH * HID];    // [r][k]  (rounded fp16)
__device__ __align__(16) __half g_Ce[HID * NCH];    // [dd][r] (rounded fp16)
__device__ __align__(16) __half g_XTh[TSEQ * HID];  // [t][k] hi
__device__ __align__(16) __half g_XTl[TSEQ * HID];  // [t][k] lo
__device__ __align__(16) float g_U[TSEQ * NCH];     // [t][r]
__device__ __align__(16) __half g_Yh[TSEQ * NCH];   // [t][r] hi
__device__ __align__(16) __half g_Yl[TSEQ * NCH];   // [t][r] lo
__device__ __align__(16) float g_carryT[NCHUNK * NPAIR * 2];  // [chunk][pair]
__device__ __align__(16) float g_super[NTILE * NPAIR * 2];    // [tile][pair]
__device__ float g_pair[NPAIR * 8];   // g, cth, sth, th, g16, c16, s16, pad

// ---------------- helpers ----------------
__device__ __forceinline__ uint32_t smem_u32(const void* p) {
    uint32_t a;
    asm("{ .reg .u64 t; cvta.to.shared.u64 t, %1; cvt.u32.u64 %0, t; }"
        : "=r"(a) : "l"(p));
    return a;
}
__device__ __forceinline__ void cp16(uint32_t s, const void* g) {
    asm volatile("cp.async.cg.shared.global [%0], [%1], 16;" :: "r"(s), "l"(g));
}
__device__ __forceinline__ void cp_commit() { asm volatile("cp.async.commit_group;"); }
__device__ __forceinline__ void cp_wait2()  { asm volatile("cp.async.wait_group 2;"); }
__device__ __forceinline__ void cp_wait1()  { asm volatile("cp.async.wait_group 1;"); }
__device__ __forceinline__ void cp_wait0()  { asm volatile("cp.async.wait_group 0;"); }

__device__ __forceinline__ void ldm4(uint32_t* r, uint32_t a) {
    asm volatile("ldmatrix.sync.aligned.m8n8.x4.shared.b16 {%0,%1,%2,%3}, [%4];"
                 : "=r"(r[0]), "=r"(r[1]), "=r"(r[2]), "=r"(r[3]) : "r"(a));
}
__device__ __forceinline__ void mma16816(float* d, const uint32_t* a, const uint32_t* b) {
    asm volatile(
        "mma.sync.aligned.m16n8k16.row.col.f32.f16.f16.f32 "
        "{%0,%1,%2,%3}, {%4,%5,%6,%7}, {%8,%9}, {%0,%1,%2,%3};"
        : "+f"(d[0]), "+f"(d[1]), "+f"(d[2]), "+f"(d[3])
        : "r"(a[0]), "r"(a[1]), "r"(a[2]), "r"(a[3]), "r"(b[0]), "r"(b[1]));
}
__device__ __forceinline__ void h_split(float x, __half& h, __half& l) {
    h = __float2half_rn(x);
    l = __float2half_rn(x - __half2float(h));
}
__device__ __forceinline__ float2 ldg64(const float2* p) {
    float2 v;
    asm volatile("ld.global.v2.f32 {%0,%1}, [%2];" : "=f"(v.x), "=f"(v.y) : "l"(p));
    return v;
}
__device__ __forceinline__ float2 cmul(float2 a, float2 b) {
    return make_float2(a.x*b.x - a.y*b.y, a.x*b.y + a.y*b.x);
}

// ============================================================
// init: blocks [0,64) = per-head setup (expm+norm+pair+W1+Ceff);
//       blocks [64,2112) = X transpose/split (fp16 hi/lo).
// ============================================================
__global__ __launch_bounds__(256) void init(const float* __restrict__ theta_log,
                                            const float* __restrict__ P,
                                            const float* __restrict__ gamma_log,
                                            const float* __restrict__ Bmat,
                                            const float* __restrict__ Cmat,
                                            const float* __restrict__ X) {
    int t = threadIdx.x;

    if (blockIdx.x >= 64) {
        __shared__ float t32[32][33];
        int b = blockIdx.x - 64;
        int tb = b & 127;
        int kb = b >> 7;
        int tx = t & 31, ty = t >> 5;
#pragma unroll
        for (int i = 0; i < 4; i++)
            t32[ty + 8*i][tx] = X[(size_t)(kb*32 + ty + 8*i) * TSEQ + tb*32 + tx];
        __syncthreads();
#pragma unroll
        for (int i = 0; i < 4; i++) {
            float v = t32[tx][ty + 8*i];
            __half hi, lo; h_split(v, hi, lo);
            size_t o = (size_t)(tb*32 + ty + 8*i) * HID + kb*32 + tx;
            g_XTh[o] = hi;
            g_XTl[o] = lo;
        }
        return;
    }

    int h = blockIdx.x;
    bool act = t < 64;
    int i = t >> 3, j = t & 7;
    __shared__ float sA[64], sT[64], sE[64];
    __shared__ float red[256];

    if (act) {
        sA[t] = 0.25f * (P[(h*8 + i)*8 + j] - P[(h*8 + j)*8 + i]);
        float id = (i == j) ? 1.f : 0.f;
        sT[t] = id;
        sE[t] = id;
    }
    __syncthreads();

    for (int k = 1; k <= 12; k++) {
        float s = 0.f;
        if (act) {
#pragma unroll
            for (int l = 0; l < 8; l++) s += sT[i*8 + l] * sA[l*8 + j];
            s *= (1.f / (float)k);
        }
        __syncthreads();
        if (act) { sT[t] = s; sE[t] += s; }
        __syncthreads();
    }
    float s1 = 0.f;
    if (act) {
#pragma unroll
        for (int l = 0; l < 8; l++) s1 += sE[i*8 + l] * sE[l*8 + j];
    }
    __syncthreads();
    if (act) sT[t] = s1;
    __syncthreads();
    float s2 = 0.f;
    if (act) {
#pragma unroll
        for (int l = 0; l < 8; l++) s2 += sT[i*8 + l] * sT[l*8 + j];
    }
    __syncthreads();
    if (act) sA[t] = s2;      // sA = final Pm

    const float4* bp = (const float4*)(Bmat + h * 8 * HID);
    float acc = 0.f;
#pragma unroll
    for (int e = 0; e < 4; e++) {
        float4 v = bp[t + e * 256];
        acc += v.x*v.x + v.y*v.y + v.z*v.z + v.w*v.w;
    }
    red[t] = acc;
    __syncthreads();
    for (int s = 128; s > 0; s >>= 1) {
        if (t < s) red[t] += red[t + s];
        __syncthreads();
    }

    float g = expf(-expf(gamma_log[h]));
    float nrm = sqrtf((1.f - g * g) / red[0]);

    if (t < 4) {
        float g2 = g*g, g4 = g2*g2, g8 = g4*g4, g16 = g8*g8;
        float th = expf(theta_log[h*4 + t]);
        float th16 = 16.f * th;
        int p = h*4 + t;
        g_pair[p*8 + 0] = g;
        g_pair[p*8 + 1] = cosf(th);
        g_pair[p*8 + 2] = sinf(th);
        g_pair[p*8 + 3] = th;
        g_pair[p*8 + 4] = g16;
        g_pair[p*8 + 5] = cosf(th16);
        g_pair[p*8 + 6] = sinf(th16);
        g_pair[p*8 + 7] = 0.f;
    }

    // W1 rows for this head (rounded fp16)
#pragma unroll
    for (int e = 0; e < 4; e++) {
        int q = t + e * 256;
        int N = q >> 7;
        int d4 = (q & 127) << 2;
        const float* pm = &sA[N*8];
        float4 a = make_float4(0.f, 0.f, 0.f, 0.f);
#pragma unroll
        for (int n = 0; n < 8; n++) {
            float4 bv = *(const float4*)&Bmat[(size_t)(h*8 + n) * HID + d4];
            float w = pm[n];
            a.x = fmaf(w, bv.x, a.x); a.y = fmaf(w, bv.y, a.y);
            a.z = fmaf(w, bv.z, a.z); a.w = fmaf(w, bv.w, a.w);
        }
        int r = h*8 + N;
        __half2 v01, v23;
        v01.x = __float2half_rn(a.x * nrm); v01.y = __float2half_rn(a.y * nrm);
        v23.x = __float2half_rn(a.z * nrm); v23.y = __float2half_rn(a.w * nrm);
        *(__half2*)&g_W1[r*HID + d4]     = v01;
        *(__half2*)&g_W1[r*HID + d4 + 2] = v23;
    }

    // Ceff columns for this head (rounded fp16)
#pragma unroll
    for (int e = 0; e < 16; e++) {
        int q = t + e * 256;
        int dd = q >> 3;
        int N = q & 7;
        const float* pm = &sA[N*8];
        float4 c0 = *(const float4*)&Cmat[(size_t)dd * NCH + h*8];
        float4 c1 = *(const float4*)&Cmat[(size_t)dd * NCH + h*8 + 4];
        float s = pm[0]*c0.x + pm[1]*c0.y + pm[2]*c0.z + pm[3]*c0.w
                + pm[4]*c1.x + pm[5]*c1.y + pm[6]*c1.z + pm[7]*c1.w;
        g_Ce[(size_t)dd * NCH + h*8 + N] = __float2half_rn(s);
    }
}

// ============================================================
// fp16 2-MMA split GEMM: D = (Ah+Al)·B, 256 threads, warp 64x32,
// 4-stage cp.async (3 tiles/stage).
// MODE 0: U + chunk carries + tile super-carries; MODE 1: out + D*x.
// ============================================================
#define PITCHB 80
#define ARRB   (128*PITCHB)   // 10240
#define STAGEB (3*ARRB)       // 30720
#define NSTAGE 4
#define PITCHF 136
#define SC_OFF 73728

template <int MODE>
__global__ __launch_bounds__(256, 1)
void gemm_mma(const __half* __restrict__ Ah, const __half* __restrict__ Al,
              const __half* __restrict__ Bw,
              float* __restrict__ Cout,
              const __half* __restrict__ Xh, const __half* __restrict__ Xl,
              const float* __restrict__ Dv) {
    extern __shared__ char smem[];
    uint32_t sb = smem_u32(smem);
    int tid = threadIdx.x, lane = tid & 31, wid = tid >> 5;
    int m0 = blockIdx.x * 128, n0 = blockIdx.y * 128;
    int m_w = (wid & 1) * 64, n_w = (wid >> 1) * 32;

    const __half* gp[3] = {Ah, Al, Bw};

    auto load_stage = [&](int s, int k0) {
        uint32_t base = sb + s * STAGEB;
#pragma unroll
        for (int a = 0; a < 3; a++) {
            int row0 = (a < 2) ? m0 : n0;
#pragma unroll
            for (int e = 0; e < 2; e++) {
                int idx = tid + e * 256;
                int row = idx >> 2, q = idx & 3;
                cp16(base + a * ARRB + row * PITCHB + q * 16,
                     gp[a] + (size_t)(row0 + row) * 512 + k0 + q * 8);
            }
        }
    };

    float acc[4][4][4];
#pragma unroll
    for (int i = 0; i < 4; i++)
#pragma unroll
        for (int j = 0; j < 4; j++)
#pragma unroll
            for (int q = 0; q < 4; q++) acc[i][j][q] = 0.f;

    load_stage(0, 0);  cp_commit();
    load_stage(1, 32); cp_commit();
    load_stage(2, 64); cp_commit();

#pragma unroll 1
    for (int kt = 0; kt < 16; kt++) {
        if (kt <= 13) cp_wait2();
        else if (kt == 14) cp_wait1();
        else cp_wait0();
        __syncthreads();
        if (kt + 3 < 16) {
            load_stage((kt + 3) & 3, (kt + 3) * 32);
            cp_commit();
        }
        uint32_t base = sb + (kt & 3) * STAGEB;

#pragma unroll
        for (int kk = 0; kk < 2; kk++) {
            int cb = kk * 32;
            uint32_t ah[4][4], al[4][4], bw[2][4];
#pragma unroll
            for (int i = 0; i < 4; i++) {
                int row = m_w + 16*i + (lane & 15);
                uint32_t ad = base + row * PITCHB + cb + 16 * (lane >> 4);
                ldm4(ah[i], ad);
                ldm4(al[i], ad + ARRB);
            }
#pragma unroll
            for (int j2 = 0; j2 < 2; j2++) {
                int n = n_w + 16*j2 + (lane & 7) + 8 * (lane >> 4);
                uint32_t ad = base + 2 * ARRB + n * PITCHB + cb + 16 * ((lane >> 3) & 1);
                ldm4(bw[j2], ad);
            }
#pragma unroll
            for (int i = 0; i < 4; i++)
#pragma unroll
                for (int j = 0; j < 4; j++)
                    mma16816(acc[i][j], ah[i], &bw[j >> 1][(j & 1) * 2]);
#pragma unroll
            for (int i = 0; i < 4; i++)
#pragma unroll
                for (int j = 0; j < 4; j++)
                    mma16816(acc[i][j], al[i], &bw[j >> 1][(j & 1) * 2]);
        }
    }

    int rh = lane >> 2, c2 = (lane & 3) * 2;

    if (MODE == 1) {
        float dvx[4], dvy[4];
#pragma unroll
        for (int j = 0; j < 4; j++) {
            int col = n0 + n_w + 8*j + c2;
            dvx[j] = Dv[col];
            dvy[j] = Dv[col + 1];
        }
#pragma unroll
        for (int i = 0; i < 4; i++) {
            int row = m0 + m_w + 16*i + rh;
#pragma unroll
            for (int j = 0; j < 4; j++) {
                int col = n0 + n_w + 8*j + c2;
                size_t o0 = (size_t)row * 512 + col;
                size_t o1 = (size_t)(row + 8) * 512 + col;
                __half2 xh0 = *(const __half2*)&Xh[o0];
                __half2 xl0 = *(const __half2*)&Xl[o0];
                __half2 xh1 = *(const __half2*)&Xh[o1];
                __half2 xl1 = *(const __half2*)&Xl[o1];
                float x00 = __half2float(xh0.x) + __half2float(xl0.x);
                float x01 = __half2float(xh0.y) + __half2float(xl0.y);
                float x10 = __half2float(xh1.x) + __half2float(xl1.x);
                float x11 = __half2float(xh1.y) + __half2float(xl1.y);
                *(float2*)&Cout[o0] = make_float2(fmaf(dvx[j], x00, acc[i][j][0]),
                                                  fmaf(dvy[j], x01, acc[i][j][1]));
                *(float2*)&Cout[o1] = make_float2(fmaf(dvx[j], x10, acc[i][j][2]),
                                                  fmaf(dvy[j], x11, acc[i][j][3]));
            }
        }
        return;
    }

    // ---------------- MODE 0 epilogue ----------------
    __syncthreads();
    float* Us = (float*)smem;   // [128][PITCHF]
#pragma unroll
    for (int i = 0; i < 4; i++) {
        int row = m_w + 16*i + rh;
#pragma unroll
        for (int j = 0; j < 4; j++) {
            int col = n_w + 8*j + c2;
            *(float2*)&Us[row * PITCHF + col]       = make_float2(acc[i][j][0], acc[i][j][1]);
            *(float2*)&Us[(row + 8) * PITCHF + col] = make_float2(acc[i][j][2], acc[i][j][3]);
        }
    }
    __syncthreads();

#pragma unroll
    for (int e = 0; e < 16; e++) {
        int idx = tid + e * 256;
        int t = idx >> 5, c4 = (idx & 31) << 2;
        float4 v = *(float4*)&Us[t * PITCHF + c4];
        *(float4*)&Cout[(size_t)(m0 + t) * 512 + n0 + c4] = v;
    }

    float2* sc = (float2*)(smem + SC_OFF);
#pragma unroll
    for (int u0 = 0; u0 < 2; u0++) {
        int u = tid + u0 * 256;
        int pl = u & 63, ch = u >> 6;
        int P = (n0 >> 1) + pl;
        float g  = g_pair[P*8 + 0];
        float gc = g * g_pair[P*8 + 1];
        float gs = g * g_pair[P*8 + 2];
        float a = 0.f, bb = 0.f;
        const float* src = &Us[(ch * 16) * PITCHF + 2 * pl];
#pragma unroll
        for (int i = 0; i < 16; i++) {
            float2 uu = *(const float2*)(src + i * PITCHF);
            float na = fmaf(gc, a, fmaf(-gs, bb, uu.x));
            float nb = fmaf(gs, a, fmaf( gc, bb, uu.y));
            a = na; bb = nb;
        }
        int C = (blockIdx.x << 3) + ch;
        *(float2*)&g_carryT[(C * NPAIR + P) * 2] = make_float2(a, bb);
        sc[ch * 64 + pl] = make_float2(a, bb);
    }
    __syncthreads();

    if (tid < 64) {
        int pl = tid;
        int P = (n0 >> 1) + pl;
        float Mx = g_pair[P*8 + 4] * g_pair[P*8 + 5];
        float My = g_pair[P*8 + 4] * g_pair[P*8 + 6];
        float2 v = sc[pl];
#pragma unroll
        for (int e = 1; e < 8; e++) {
            float2 cb2 = sc[e * 64 + pl];
            v = make_float2(fmaf(Mx, v.x, fmaf(-My, v.y, cb2.x)),
                            fmaf(Mx, v.y, fmaf( My, v.x, cb2.y)));
        }
        *(float2*)&g_super[((int)blockIdx.x * NPAIR + P) * 2] = v;
    }
}

// ============================================================
// scan3: block c handles rows [c*16, c*16+16); thread p = pair.
// Seed = chain over tile super-carries (M^8) then chunk carries (M).
// ============================================================
__global__ __launch_bounds__(256, 1) void scan3() {
    int c = blockIdx.x;
    int p = threadIdx.x;
    int tb = c >> 3;
    int ci = c & 7;

    float g  = g_pair[p*8 + 0];
    float gc = g * g_pair[p*8 + 1];
    float gs = g * g_pair[p*8 + 2];
    float2 M = make_float2(g_pair[p*8 + 4] * g_pair[p*8 + 5],
                           g_pair[p*8 + 4] * g_pair[p*8 + 6]);
    float2 M8 = cmul(M, M); M8 = cmul(M8, M8); M8 = cmul(M8, M8);

    float a = 0.f, b = 0.f;
    float2 ub[8];

    {
        const float2* sp = (const float2*)g_super + p;
        int k = 0;
#pragma unroll 1
        for (; k + 8 <= tb; k += 8) {
#pragma unroll
            for (int e = 0; e < 8; e++) ub[e] = ldg64(sp + (k + e) * NPAIR);
#pragma unroll
            for (int e = 0; e < 8; e++) {
                float na = fmaf(M8.x, a, fmaf(-M8.y, b, ub[e].x));
                float nb = fmaf(M8.x, b, fmaf( M8.y, a, ub[e].y));
                a = na; b = nb;
            }
        }
#pragma unroll 1
        for (; k < tb; k++) {
            float2 v = ldg64(sp + k * NPAIR);
            float na = fmaf(M8.x, a, fmaf(-M8.y, b, v.x));
            float nb = fmaf(M8.x, b, fmaf( M8.y, a, v.y));
            a = na; b = nb;
        }
    }
    {
        const float2* cp = (const float2*)g_carryT + (size_t)(tb * 8) * NPAIR + p;
#pragma unroll 1
        for (int k = 0; k < ci; k++) {
            float2 v = ldg64(cp + k * NPAIR);
            float na = fmaf(M.x, a, fmaf(-M.y, b, v.x));
            float nb = fmaf(M.x, b, fmaf( M.y, a, v.y));
            a = na; b = nb;
        }
    }

    const float2* up = (const float2*)(g_U + (size_t)(c * CHUNK) * NCH) + p;
    __half2* yh = (__half2*)(g_Yh + (size_t)(c * CHUNK) * NCH) + p;
    __half2* yl = (__half2*)(g_Yl + (size_t)(c * CHUNK) * NCH) + p;

#pragma unroll
    for (int base = 0; base < CHUNK; base += 8) {
#pragma unroll
        for (int e = 0; e < 8; e++) ub[e] = ldg64(up + (base + e) * 256);
#pragma unroll
        for (int e = 0; e < 8; e++) {
            float na = fmaf(gc, a, fmaf(-gs, b, ub[e].x));
            float nb = fmaf(gs, a, fmaf( gc, b, ub[e].y));
            a = na; b = nb;
            __half ha, la, hb, lb;
            h_split(a, ha, la);
            h_split(b, hb, lb);
            __half2 vh; vh.x = ha; vh.y = hb;
            __half2 vl; vl.x = la; vl.y = lb;
            yh[(base + e) * 256] = vh;
            yl[(base + e) * 256] = vl;
        }
    }
}

// ============================================================
extern "C" void kernel_launch(void* const* d_in, const int* in_sizes, int n_in,
                              void* d_out, int out_size) {
    const float* X         = (const float*)d_in[0];
    const float* theta_log = (const float*)d_in[1];
    const float* P         = (const float*)d_in[2];
    const float* Bmat      = (const float*)d_in[3];
    const float* Cmat      = (const float*)d_in[4];
    const float* Dv        = (const float*)d_in[5];
    const float* gamma_log = (const float*)d_in[6];
    float* out = (float*)d_out;

    const int GEMM_SMEM = NSTAGE * STAGEB;   // 122880
    cudaFuncSetAttribute(gemm_mma<0>, cudaFuncAttributeMaxDynamicSharedMemorySize, GEMM_SMEM);
    cudaFuncSetAttribute(gemm_mma<1>, cudaFuncAttributeMaxDynamicSharedMemorySize, GEMM_SMEM);

    init<<<2112, 256>>>(theta_log, P, gamma_log, Bmat, Cmat, X);

    float* U;   cudaGetSymbolAddress((void**)&U, g_U);
    __half *XTh, *XTl, *W1, *Yh, *Yl, *Ce;
    cudaGetSymbolAddress((void**)&XTh, g_XTh);
    cudaGetSymbolAddress((void**)&XTl, g_XTl);
    cudaGetSymbolAddress((void**)&W1, g_W1);
    cudaGetSymbolAddress((void**)&Yh, g_Yh);
    cudaGetSymbolAddress((void**)&Yl, g_Yl);
    cudaGetSymbolAddress((void**)&Ce, g_Ce);

    dim3 gg(TSEQ / 128, NCH / 128);   // (32, 4)
    gemm_mma<0><<<gg, 256, GEMM_SMEM>>>(XTh, XTl, W1, U, nullptr, nullptr, nullptr);
    scan3<<<NCHUNK, 256>>>();
    gemm_mma<1><<<gg, 256, GEMM_SMEM>>>(Yh, Yl, Ce, out, XTh, XTl, Dv);
}